// round 1
// baseline (speedup 1.0000x reference)
#include <cuda_runtime.h>
#include <math.h>

#define N_FIELDS 8
#define HIDDEN   128
#define GEO      15
#define APP      32
#define CIN      50     // 3 dir + 15 geo + 32 app
#define CINP     52     // padded to multiple of 4
#define N_MAX    524288
#define TILE     128

// ---------------- device scratch (static globals, no allocation) -----------
__device__ int g_counts[N_FIELDS];
__device__ int g_bucket[N_FIELDS][N_MAX];

// ---------------- kernel 0: zero counters ----------------------------------
__global__ void k_zero() {
    if (threadIdx.x < N_FIELDS) g_counts[threadIdx.x] = 0;
}

// ---------------- kernel 1: assign + warp-aggregated scatter ---------------
__global__ void k_assign(const float* __restrict__ pos,
                         const float* __restrict__ cent, int n) {
    int i = blockIdx.x * blockDim.x + threadIdx.x;
    unsigned act = __ballot_sync(0xffffffffu, i < n);
    if (i >= n) return;

    float px = pos[3*i], py = pos[3*i+1], pz = pos[3*i+2];
    int best = 0; float bd = 3.402823e38f;
    #pragma unroll
    for (int c = 0; c < N_FIELDS; c++) {
        float dx = px - __ldg(&cent[3*c+0]);
        float dy = py - __ldg(&cent[3*c+1]);
        float dz = pz - __ldg(&cent[3*c+2]);
        float d = dx*dx + dy*dy + dz*dz;
        if (d < bd) { bd = d; best = c; }   // strict <  => first min wins (argmin semantics)
    }

    unsigned peers  = __match_any_sync(act, best);
    int      leader = __ffs(peers) - 1;
    int      lane   = threadIdx.x & 31;
    int base = 0;
    if (lane == leader) base = atomicAdd(&g_counts[best], __popc(peers));
    base = __shfl_sync(peers, base, leader);
    int slot = base + __popc(peers & ((1u << lane) - 1u));
    g_bucket[best][slot] = i;
}

// ---------------- kernel 2: per-field dense MLP -----------------------------
__global__ void __launch_bounds__(TILE)
k_field(const float* __restrict__ pos, const float* __restrict__ dir,
        const float* __restrict__ app,
        const float* __restrict__ Wd1, const float* __restrict__ bd1,
        const float* __restrict__ Wd2, const float* __restrict__ bd2,
        const float* __restrict__ Wc1, const float* __restrict__ bc1,
        const float* __restrict__ Wc2, const float* __restrict__ bc2,
        float* __restrict__ out, int tpf)
{
    __shared__ float sWd1[3*HIDDEN];
    __shared__ float sbd1[HIDDEN];
    __shared__ float sWd2[HIDDEN*16];
    __shared__ float sbd2[16];
    __shared__ float sWc1[HIDDEN*CINP];   // transposed: [j][k], k padded to 52
    __shared__ float sbc1[HIDDEN];
    __shared__ float sWc2[HIDDEN*4];      // [j][0..2] + pad
    __shared__ float sbc2[4];

    int f = blockIdx.x / tpf;
    int t = blockIdx.x - f * tpf;
    int cnt = g_counts[f];
    if (t * TILE >= cnt) return;

    int tid = threadIdx.x;

    // ---- stage weights into smem ----
    {
        const float* g = Wd1 + f*3*HIDDEN;
        for (int i = tid; i < 3*HIDDEN; i += TILE) sWd1[i] = g[i];
    }
    {
        const float* g = bd1 + f*HIDDEN;
        for (int i = tid; i < HIDDEN; i += TILE) sbd1[i] = g[i];
    }
    {
        const float* g = Wd2 + f*HIDDEN*16;
        for (int i = tid; i < HIDDEN*16; i += TILE) sWd2[i] = g[i];
    }
    if (tid < 16) sbd2[tid] = bd2[f*16 + tid];
    {   // transpose Wc1 [k][j] -> sWc1 [j][k]
        const float* g = Wc1 + f*CIN*HIDDEN;
        for (int i = tid; i < CIN*HIDDEN; i += TILE) {
            int k = i / HIDDEN, j = i - k*HIDDEN;
            sWc1[j*CINP + k] = g[i];
        }
        sWc1[tid*CINP + 50] = 0.f;   // zero pads (tid spans 0..127 == all j)
        sWc1[tid*CINP + 51] = 0.f;
    }
    {
        const float* g = bc1 + f*HIDDEN;
        for (int i = tid; i < HIDDEN; i += TILE) sbc1[i] = g[i];
    }
    {
        const float* g = Wc2 + f*HIDDEN*3;
        for (int i = tid; i < HIDDEN; i += TILE) {
            sWc2[i*4+0] = g[i*3+0];
            sWc2[i*4+1] = g[i*3+1];
            sWc2[i*4+2] = g[i*3+2];
            sWc2[i*4+3] = 0.f;
        }
    }
    if (tid < 3) sbc2[tid] = bc2[f*3 + tid];
    if (tid == 3) sbc2[3] = 0.f;
    __syncthreads();

    int bi = t * TILE + tid;
    if (bi >= cnt) return;
    int p = g_bucket[f][bi];

    float px = pos[3*p], py = pos[3*p+1], pz = pos[3*p+2];

    // ---- layer 1: h = relu(pos @ Wd1 + bd1), h kept in registers ----
    float h[HIDDEN];
    #pragma unroll
    for (int j = 0; j < HIDDEN; j += 4) {
        float4 w0 = *(const float4*)&sWd1[0*HIDDEN + j];
        float4 w1 = *(const float4*)&sWd1[1*HIDDEN + j];
        float4 w2 = *(const float4*)&sWd1[2*HIDDEN + j];
        float4 b  = *(const float4*)&sbd1[j];
        h[j+0] = fmaxf(fmaf(px,w0.x,fmaf(py,w1.x,fmaf(pz,w2.x,b.x))), 0.f);
        h[j+1] = fmaxf(fmaf(px,w0.y,fmaf(py,w1.y,fmaf(pz,w2.y,b.y))), 0.f);
        h[j+2] = fmaxf(fmaf(px,w0.z,fmaf(py,w1.z,fmaf(pz,w2.z,b.z))), 0.f);
        h[j+3] = fmaxf(fmaf(px,w0.w,fmaf(py,w1.w,fmaf(pz,w2.w,b.w))), 0.f);
    }

    // ---- layer 2: dout = h @ Wd2 + bd2 (16 independent accumulators) ----
    float d0[16];
    #pragma unroll
    for (int j = 0; j < 16; j++) d0[j] = sbd2[j];
    #pragma unroll
    for (int k = 0; k < HIDDEN; k++) {
        float hk = h[k];
        const float4* wr = (const float4*)&sWd2[k*16];
        #pragma unroll
        for (int q = 0; q < 4; q++) {
            float4 w = wr[q];
            d0[4*q+0] = fmaf(hk, w.x, d0[4*q+0]);
            d0[4*q+1] = fmaf(hk, w.y, d0[4*q+1]);
            d0[4*q+2] = fmaf(hk, w.z, d0[4*q+2]);
            d0[4*q+3] = fmaf(hk, w.w, d0[4*q+3]);
        }
    }
    float density = expf(d0[0]);

    // ---- build cin = [dir, geo, app] (padded to 52) ----
    float cin[CINP];
    cin[0] = dir[3*p]; cin[1] = dir[3*p+1]; cin[2] = dir[3*p+2];
    #pragma unroll
    for (int g = 0; g < GEO; g++) cin[3+g] = d0[1+g];
    {
        const float4* ap = (const float4*)(app + (size_t)p*APP);
        #pragma unroll
        for (int q = 0; q < APP/4; q++) {
            float4 v = __ldg(&ap[q]);
            cin[18+4*q+0] = v.x; cin[18+4*q+1] = v.y;
            cin[18+4*q+2] = v.z; cin[18+4*q+3] = v.w;
        }
    }
    cin[50] = 0.f; cin[51] = 0.f;

    // ---- color MLP fused: rgb += relu(cin @ Wc1[:,j] + bc1[j]) * Wc2[j,:] ----
    float r0 = sbc2[0], r1 = sbc2[1], r2 = sbc2[2];
    #pragma unroll 4
    for (int j = 0; j < HIDDEN; j++) {
        float acc = sbc1[j];
        const float4* wr = (const float4*)&sWc1[j*CINP];
        #pragma unroll
        for (int q = 0; q < CINP/4; q++) {
            float4 w = wr[q];
            acc = fmaf(cin[4*q+0], w.x, acc);
            acc = fmaf(cin[4*q+1], w.y, acc);
            acc = fmaf(cin[4*q+2], w.z, acc);
            acc = fmaf(cin[4*q+3], w.w, acc);
        }
        float hc = fmaxf(acc, 0.f);
        float4 w2 = *(const float4*)&sWc2[j*4];
        r0 = fmaf(hc, w2.x, r0);
        r1 = fmaf(hc, w2.y, r1);
        r2 = fmaf(hc, w2.z, r2);
    }

    float4 o;
    o.x = density;
    o.y = 1.f / (1.f + expf(-r0));
    o.z = 1.f / (1.f + expf(-r1));
    o.w = 1.f / (1.f + expf(-r2));
    *(float4*)&out[(size_t)4*p] = o;
}

// ---------------- launch ----------------------------------------------------
extern "C" void kernel_launch(void* const* d_in, const int* in_sizes, int n_in,
                              void* d_out, int out_size) {
    const float* positions = (const float*)d_in[0];
    const float* directions = (const float*)d_in[1];
    const float* appearance = (const float*)d_in[2];
    const float* centroids  = (const float*)d_in[3];
    const float* Wd1 = (const float*)d_in[4];
    const float* bd1 = (const float*)d_in[5];
    const float* Wd2 = (const float*)d_in[6];
    const float* bd2 = (const float*)d_in[7];
    const float* Wc1 = (const float*)d_in[8];
    const float* bc1 = (const float*)d_in[9];
    const float* Wc2 = (const float*)d_in[10];
    const float* bc2 = (const float*)d_in[11];
    float* out = (float*)d_out;

    int n = in_sizes[0] / 3;
    if (n > N_MAX) n = N_MAX;

    int tpf = (n + TILE - 1) / TILE;   // one field may own all points

    k_zero<<<1, 32>>>();
    k_assign<<<(n + 255) / 256, 256>>>(positions, centroids, n);
    k_field<<<N_FIELDS * tpf, TILE>>>(positions, directions, appearance,
                                      Wd1, bd1, Wd2, bd2, Wc1, bc1, Wc2, bc2,
                                      out, tpf);
}